// round 3
// baseline (speedup 1.0000x reference)
#include <cuda_runtime.h>
#include <cuda_bf16.h>

// Shapes (fixed by the problem)
#define L_DIM 4
#define B_DIM 8
#define C_DIM 256
#define HW    4096                       // 64*64
#define LBC   (L_DIM * B_DIM * C_DIM)    // 8192
#define B_PER_SLICE 2
#define N_SLICES    (B_DIM / B_PER_SLICE)            // 4
#define PLANES_PER_SLICE (L_DIM * B_PER_SLICE * C_DIM)  // 2048

// Scratch in device globals (no allocations allowed)
__device__ float g_gap[LBC];
__device__ float g_attn[LBC];

// Map slice-local block id -> global plane id (l*B + b)*C + c
__device__ __forceinline__ int slice_plane(int blk, int s) {
    int l  = blk >> 9;            // /512
    int bb = (blk >> 8) & 1;      // which batch within slice
    int c  = blk & 255;
    int b  = s * B_PER_SLICE + bb;
    return (l * B_DIM + b) * C_DIM + c;
}

// ---------------------------------------------------------------------------
// GAP over one slice (2 batches): 2048 blocks x 128 threads.
// Each block reduces one contiguous 4096-float plane.
// ---------------------------------------------------------------------------
__global__ __launch_bounds__(128) void gap_slice(const float* __restrict__ in, int s) {
    const int bc = slice_plane(blockIdx.x, s);
    const float4* p = reinterpret_cast<const float4*>(in) + (size_t)bc * (HW / 4);
    const int t = threadIdx.x;

    float sum = 0.0f;
#pragma unroll
    for (int k = 0; k < 8; ++k) {
        float4 v = p[t + k * 128];
        sum += (v.x + v.y) + (v.z + v.w);
    }
#pragma unroll
    for (int o = 16; o > 0; o >>= 1)
        sum += __shfl_xor_sync(0xffffffffu, sum, o);

    __shared__ float sh[4];
    if ((t & 31) == 0) sh[t >> 5] = sum;
    __syncthreads();
    if (t == 0)
        g_gap[bc] = (sh[0] + sh[1] + sh[2] + sh[3]) * (1.0f / (float)HW);
}

// ---------------------------------------------------------------------------
// attn for one slice: 2 blocks (one per batch), 256 threads (one per out ch).
// ---------------------------------------------------------------------------
__global__ __launch_bounds__(C_DIM) void attn_slice(const float* __restrict__ Wlin, int s) {
    const int b = s * B_PER_SLICE + blockIdx.x;
    const int d = threadIdx.x;

    __shared__ float gs[L_DIM][C_DIM];
    for (int i = threadIdx.x; i < L_DIM * C_DIM; i += blockDim.x) {
        int l = i >> 8;
        int c = i & 255;
        gs[l][c] = g_gap[(l * B_DIM + b) * C_DIM + c];
    }
    __syncthreads();

    float acc[L_DIM] = {0.f, 0.f, 0.f, 0.f};
    const float* wr = Wlin + (size_t)d * C_DIM;
#pragma unroll 4
    for (int c = 0; c < C_DIM; ++c) {
        float w = wr[c];
#pragma unroll
        for (int l = 0; l < L_DIM; ++l)
            acc[l] = fmaf(w, gs[l][c], acc[l]);
    }

    float m = fmaxf(fmaxf(acc[0], acc[1]), fmaxf(acc[2], acc[3]));
    float e[L_DIM];
    float sum = 0.0f;
#pragma unroll
    for (int l = 0; l < L_DIM; ++l) {
        e[l] = __expf(acc[l] - m);
        sum += e[l];
    }
    float inv = 1.0f / sum;
#pragma unroll
    for (int l = 0; l < L_DIM; ++l)
        g_attn[(l * B_DIM + b) * C_DIM + d] = e[l] * inv;
}

// ---------------------------------------------------------------------------
// Scale one slice: 2048 blocks x 256 threads, one plane per block.
// Reads should hit L2 (slice input was just streamed by gap_slice and the
// 64 MB slice working set fits the 126 MB L2). Plain loads/stores.
// ---------------------------------------------------------------------------
__global__ __launch_bounds__(256) void scale_slice(const float* __restrict__ in,
                                                   float* __restrict__ out, int s) {
    const int bc = slice_plane(blockIdx.x, s);
    const float a = g_attn[bc];
    const float4* p = reinterpret_cast<const float4*>(in) + (size_t)bc * (HW / 4);
    float4* o = reinterpret_cast<float4*>(out) + (size_t)bc * (HW / 4);
    const int t = threadIdx.x;
#pragma unroll
    for (int k = 0; k < 4; ++k) {
        float4 v = p[t + k * 256];
        v.x *= a; v.y *= a; v.z *= a; v.w *= a;
        o[t + k * 256] = v;
    }
}

extern "C" void kernel_launch(void* const* d_in, const int* in_sizes, int n_in,
                              void* d_out, int out_size) {
    const float* inputs = (const float*)d_in[0];   // [L,B,C,H,W] f32
    const float* Wlin   = (const float*)d_in[1];   // [C,C] f32
    float* out = (float*)d_out;

    for (int s = 0; s < N_SLICES; ++s) {
        gap_slice<<<PLANES_PER_SLICE, 128>>>(inputs, s);
        attn_slice<<<B_PER_SLICE, C_DIM>>>(Wlin, s);
        scale_slice<<<PLANES_PER_SLICE, 256>>>(inputs, out, s);
    }
}

// round 4
// speedup vs baseline: 2.1579x; 2.1579x over previous
#include <cuda_runtime.h>
#include <cuda_bf16.h>

// Shapes (fixed by the problem)
#define L_DIM 4
#define B_DIM 8
#define C_DIM 256
#define HW    4096           // 64*64
#define LBC   (L_DIM * B_DIM * C_DIM)   // 8192

// Scratch in device globals (no allocations allowed)
__device__ float g_gap[LBC];
__device__ float g_attn[LBC];

// ---------------------------------------------------------------------------
// Kernel 1: GAP over H,W. One block per (l,b,c) plane (4096 contiguous f32).
// 128 threads, each loads 8 float4 (32 floats), warp-shuffle reduce.
// (Identical to the 104.5us R1 version — it runs at ~6 TB/s.)
// ---------------------------------------------------------------------------
__global__ __launch_bounds__(128) void gap_kernel(const float* __restrict__ in) {
    const int bc = blockIdx.x;                     // 0..8191, linear (l,b,c)
    const float4* p = reinterpret_cast<const float4*>(in) + (size_t)bc * (HW / 4);
    const int t = threadIdx.x;

    float s = 0.0f;
#pragma unroll
    for (int k = 0; k < 8; ++k) {
        float4 v = p[t + k * 128];
        s += (v.x + v.y) + (v.z + v.w);
    }
#pragma unroll
    for (int o = 16; o > 0; o >>= 1)
        s += __shfl_xor_sync(0xffffffffu, s, o);

    __shared__ float sh[4];
    if ((t & 31) == 0) sh[t >> 5] = s;
    __syncthreads();
    if (t == 0)
        g_gap[bc] = (sh[0] + sh[1] + sh[2] + sh[3]) * (1.0f / (float)HW);
}

// ---------------------------------------------------------------------------
// Kernel 2 (REWRITTEN): scores = gap @ W^T, softmax over L per (b, d).
// 8 blocks (one per b), 256 threads = 8 warps. Warp w owns d in [32w, 32w+32).
// For each d, the 32 lanes read W[d][lane + 32j] — one coalesced 128B line
// per iteration — FMA against smem gap for all 4 L's, then shuffle-reduce.
// Replaces the old 32-way-uncoalesced per-thread row walk (~35us -> ~3us).
// ---------------------------------------------------------------------------
__global__ __launch_bounds__(C_DIM) void attn_kernel(const float* __restrict__ Wlin) {
    const int b = blockIdx.x;
    const int t = threadIdx.x;
    const int warp = t >> 5;
    const int lane = t & 31;

    __shared__ float gs[L_DIM][C_DIM];
    for (int i = t; i < L_DIM * C_DIM; i += blockDim.x) {
        int l = i >> 8;
        int c = i & 255;
        gs[l][c] = g_gap[(l * B_DIM + b) * C_DIM + c];
    }
    __shared__ float s_scores[L_DIM][C_DIM];
    __syncthreads();

    // Each warp computes scores for 32 output channels.
#pragma unroll 1
    for (int dd = 0; dd < 32; ++dd) {
        const int d = warp * 32 + dd;
        const float* wr = Wlin + (size_t)d * C_DIM;
        float acc0 = 0.f, acc1 = 0.f, acc2 = 0.f, acc3 = 0.f;
#pragma unroll
        for (int j = 0; j < C_DIM / 32; ++j) {
            const int c = lane + 32 * j;
            float w = wr[c];                     // coalesced across the warp
            acc0 = fmaf(w, gs[0][c], acc0);
            acc1 = fmaf(w, gs[1][c], acc1);
            acc2 = fmaf(w, gs[2][c], acc2);
            acc3 = fmaf(w, gs[3][c], acc3);
        }
#pragma unroll
        for (int o = 16; o > 0; o >>= 1) {
            acc0 += __shfl_xor_sync(0xffffffffu, acc0, o);
            acc1 += __shfl_xor_sync(0xffffffffu, acc1, o);
            acc2 += __shfl_xor_sync(0xffffffffu, acc2, o);
            acc3 += __shfl_xor_sync(0xffffffffu, acc3, o);
        }
        if (lane == 0) {
            s_scores[0][d] = acc0;
            s_scores[1][d] = acc1;
            s_scores[2][d] = acc2;
            s_scores[3][d] = acc3;
        }
    }
    __syncthreads();

    // Softmax over L for channel t, write attn.
    const int d = t;
    float a0 = s_scores[0][d], a1 = s_scores[1][d];
    float a2 = s_scores[2][d], a3 = s_scores[3][d];
    float m = fmaxf(fmaxf(a0, a1), fmaxf(a2, a3));
    float e0 = __expf(a0 - m), e1 = __expf(a1 - m);
    float e2 = __expf(a2 - m), e3 = __expf(a3 - m);
    float inv = 1.0f / (e0 + e1 + e2 + e3);
    g_attn[(0 * B_DIM + b) * C_DIM + d] = e0 * inv;
    g_attn[(1 * B_DIM + b) * C_DIM + d] = e1 * inv;
    g_attn[(2 * B_DIM + b) * C_DIM + d] = e2 * inv;
    g_attn[(3 * B_DIM + b) * C_DIM + d] = e3 * inv;
}

// ---------------------------------------------------------------------------
// Kernel 3: out = in * attn (broadcast per (l,b,c) plane).
// One block per plane; 256 threads x 4 float4 each = 4096 floats.
// (Identical to the 104.5us R1 version.)
// ---------------------------------------------------------------------------
__global__ __launch_bounds__(256) void scale_kernel(const float* __restrict__ in,
                                                    float* __restrict__ out) {
    const int bc = blockIdx.x;
    const float a = g_attn[bc];
    const float4* p = reinterpret_cast<const float4*>(in) + (size_t)bc * (HW / 4);
    float4* o = reinterpret_cast<float4*>(out) + (size_t)bc * (HW / 4);
    const int t = threadIdx.x;
#pragma unroll
    for (int k = 0; k < 4; ++k) {
        float4 v = p[t + k * 256];
        v.x *= a; v.y *= a; v.z *= a; v.w *= a;
        o[t + k * 256] = v;
    }
}

extern "C" void kernel_launch(void* const* d_in, const int* in_sizes, int n_in,
                              void* d_out, int out_size) {
    const float* inputs = (const float*)d_in[0];   // [L,B,C,H,W] f32
    const float* Wlin   = (const float*)d_in[1];   // [C,C] f32
    float* out = (float*)d_out;

    gap_kernel<<<LBC, 128>>>(inputs);
    attn_kernel<<<B_DIM, C_DIM>>>(Wlin);
    scale_kernel<<<LBC, 256>>>(inputs, out);
}

// round 5
// speedup vs baseline: 2.2310x; 1.0339x over previous
#include <cuda_runtime.h>
#include <cuda_bf16.h>

// Shapes (fixed by the problem)
#define L_DIM 4
#define B_DIM 8
#define C_DIM 256
#define HW    4096           // 64*64
#define LBC   (L_DIM * B_DIM * C_DIM)   // 8192

// Scratch in device globals (no allocations allowed)
__device__ float g_gap[LBC];
__device__ float g_attn[LBC];

// ---------------------------------------------------------------------------
// Kernel 1: GAP over H,W. One block per (l,b,c) plane (4096 contiguous f32).
// 128 threads, each loads 8 float4 (32 floats), warp-shuffle reduce.
// (Unchanged — runs at ~6 TB/s, 75% DRAM.)
// ---------------------------------------------------------------------------
__global__ __launch_bounds__(128) void gap_kernel(const float* __restrict__ in) {
    const int bc = blockIdx.x;                     // 0..8191, linear (l,b,c)
    const float4* p = reinterpret_cast<const float4*>(in) + (size_t)bc * (HW / 4);
    const int t = threadIdx.x;

    float s = 0.0f;
#pragma unroll
    for (int k = 0; k < 8; ++k) {
        float4 v = p[t + k * 128];
        s += (v.x + v.y) + (v.z + v.w);
    }
#pragma unroll
    for (int o = 16; o > 0; o >>= 1)
        s += __shfl_xor_sync(0xffffffffu, s, o);

    __shared__ float sh[4];
    if ((t & 31) == 0) sh[t >> 5] = s;
    __syncthreads();
    if (t == 0)
        g_gap[bc] = (sh[0] + sh[1] + sh[2] + sh[3]) * (1.0f / (float)HW);
}

// ---------------------------------------------------------------------------
// Kernel 2: scores = gap @ W^T, softmax over L per (b, d). 8 blocks, 8 warps.
// Warp-coalesced W reads + shuffle reduction. (Unchanged from R4.)
// ---------------------------------------------------------------------------
__global__ __launch_bounds__(C_DIM) void attn_kernel(const float* __restrict__ Wlin) {
    const int b = blockIdx.x;
    const int t = threadIdx.x;
    const int warp = t >> 5;
    const int lane = t & 31;

    __shared__ float gs[L_DIM][C_DIM];
    for (int i = t; i < L_DIM * C_DIM; i += blockDim.x) {
        int l = i >> 8;
        int c = i & 255;
        gs[l][c] = g_gap[(l * B_DIM + b) * C_DIM + c];
    }
    __shared__ float s_scores[L_DIM][C_DIM];
    __syncthreads();

#pragma unroll 1
    for (int dd = 0; dd < 32; ++dd) {
        const int d = warp * 32 + dd;
        const float* wr = Wlin + (size_t)d * C_DIM;
        float acc0 = 0.f, acc1 = 0.f, acc2 = 0.f, acc3 = 0.f;
#pragma unroll
        for (int j = 0; j < C_DIM / 32; ++j) {
            const int c = lane + 32 * j;
            float w = wr[c];                     // coalesced across the warp
            acc0 = fmaf(w, gs[0][c], acc0);
            acc1 = fmaf(w, gs[1][c], acc1);
            acc2 = fmaf(w, gs[2][c], acc2);
            acc3 = fmaf(w, gs[3][c], acc3);
        }
#pragma unroll
        for (int o = 16; o > 0; o >>= 1) {
            acc0 += __shfl_xor_sync(0xffffffffu, acc0, o);
            acc1 += __shfl_xor_sync(0xffffffffu, acc1, o);
            acc2 += __shfl_xor_sync(0xffffffffu, acc2, o);
            acc3 += __shfl_xor_sync(0xffffffffu, acc3, o);
        }
        if (lane == 0) {
            s_scores[0][d] = acc0;
            s_scores[1][d] = acc1;
            s_scores[2][d] = acc2;
            s_scores[3][d] = acc3;
        }
    }
    __syncthreads();

    const int d = t;
    float a0 = s_scores[0][d], a1 = s_scores[1][d];
    float a2 = s_scores[2][d], a3 = s_scores[3][d];
    float m = fmaxf(fmaxf(a0, a1), fmaxf(a2, a3));
    float e0 = __expf(a0 - m), e1 = __expf(a1 - m);
    float e2 = __expf(a2 - m), e3 = __expf(a3 - m);
    float inv = 1.0f / (e0 + e1 + e2 + e3);
    g_attn[(0 * B_DIM + b) * C_DIM + d] = e0 * inv;
    g_attn[(1 * B_DIM + b) * C_DIM + d] = e1 * inv;
    g_attn[(2 * B_DIM + b) * C_DIM + d] = e2 * inv;
    g_attn[(3 * B_DIM + b) * C_DIM + d] = e3 * inv;
}

// ---------------------------------------------------------------------------
// Kernel 3 (REWRITTEN): out = in * attn. Mirrors gap_kernel's proven access
// shape: 128 threads/block, 8 independent float4 loads front-batched into
// distinct registers (MLP_p1=8), attn scalar loaded while they're in flight,
// then 8 stores at the tail. One block per plane.
// ---------------------------------------------------------------------------
__global__ __launch_bounds__(128) void scale_kernel(const float* __restrict__ in,
                                                    float* __restrict__ out) {
    const int bc = blockIdx.x;
    const float4* p = reinterpret_cast<const float4*>(in) + (size_t)bc * (HW / 4);
    float4* o = reinterpret_cast<float4*>(out) + (size_t)bc * (HW / 4);
    const int t = threadIdx.x;

    // Front-batch all 8 loads (independent -> 8 LDG.128 in flight per thread).
    float4 v0 = p[t + 0 * 128];
    float4 v1 = p[t + 1 * 128];
    float4 v2 = p[t + 2 * 128];
    float4 v3 = p[t + 3 * 128];
    float4 v4 = p[t + 4 * 128];
    float4 v5 = p[t + 5 * 128];
    float4 v6 = p[t + 6 * 128];
    float4 v7 = p[t + 7 * 128];

    // attn scalar latency hides under the 8 outstanding data loads.
    const float a = __ldg(&g_attn[bc]);

    v0.x *= a; v0.y *= a; v0.z *= a; v0.w *= a;
    v1.x *= a; v1.y *= a; v1.z *= a; v1.w *= a;
    v2.x *= a; v2.y *= a; v2.z *= a; v2.w *= a;
    v3.x *= a; v3.y *= a; v3.z *= a; v3.w *= a;
    v4.x *= a; v4.y *= a; v4.z *= a; v4.w *= a;
    v5.x *= a; v5.y *= a; v5.z *= a; v5.w *= a;
    v6.x *= a; v6.y *= a; v6.z *= a; v6.w *= a;
    v7.x *= a; v7.y *= a; v7.z *= a; v7.w *= a;

    o[t + 0 * 128] = v0;
    o[t + 1 * 128] = v1;
    o[t + 2 * 128] = v2;
    o[t + 3 * 128] = v3;
    o[t + 4 * 128] = v4;
    o[t + 5 * 128] = v5;
    o[t + 6 * 128] = v6;
    o[t + 7 * 128] = v7;
}

extern "C" void kernel_launch(void* const* d_in, const int* in_sizes, int n_in,
                              void* d_out, int out_size) {
    const float* inputs = (const float*)d_in[0];   // [L,B,C,H,W] f32
    const float* Wlin   = (const float*)d_in[1];   // [C,C] f32
    float* out = (float*)d_out;

    gap_kernel<<<LBC, 128>>>(inputs);
    attn_kernel<<<B_DIM, C_DIM>>>(Wlin);
    scale_kernel<<<LBC, 128>>>(inputs, out);
}